// round 17
// baseline (speedup 1.0000x reference)
#include <cuda_runtime.h>
#include <cuda_bf16.h>
#include <mma.h>
#include <cstddef>
#include <cstdint>

using namespace nvcuda;

// Problem constants (fixed by setup_inputs)
constexpr int D      = 64;
constexpr int N      = 128;
constexpr int NSTEPS = 16;

constexpr int MROWS = D * D;       // 4096 = (i,a)
constexpr int NCOLS = N * D;       // 8192 = (n,b)

// ---------------- device scratch (no allocations allowed) ----------------
__device__ __align__(16) float g_RP[NSTEPS][D * D];  // [k][a*64+c] = Xp_k[a][c]
// Split-bf16 operands (a ~= a0 + a1, 16 effective mantissa bits)
__device__ __align__(16) __nv_bfloat16 g_A0[MROWS * NSTEPS];   // A[r][s], r=(i,a)
__device__ __align__(16) __nv_bfloat16 g_A1[MROWS * NSTEPS];
__device__ __align__(16) __nv_bfloat16 g_B0[NSTEPS * NCOLS];   // B[s][c], c=(n,b)
__device__ __align__(16) __nv_bfloat16 g_B1[NSTEPS * NCOLS];

__device__ __forceinline__ void bf16split(float f, __nv_bfloat16& h0,
                                          __nv_bfloat16& h1) {
    h0 = __float2bfloat16_rn(f);
    h1 = __float2bfloat16_rn(f - __bfloat162float(h0));
}

// KPREP: direct row-wise simulation of BOTH systems.
//   rows 0..127   : state rows (x0, v0) -> g_B0/g_B1 splits (coalesced 4B
//                   bf16x2 stores) + traj frames. g_X eliminated.
//   rows 128..191 : propagator rows a: X0 = dt^2*e_a, V0 = dt*e_a
//                   -> g_RP[k] row-major f32 (coalesced; transpose in ksplitA).
// One warp per row; lane owns 2 columns; double-buffered sX -> ONE syncwarp
// per step. W staged transposed in smem. M[k][c] = W[c][k] - delta(k,c).
__global__ void __launch_bounds__(128) kprep(const float* __restrict__ x0,
                                             const float* __restrict__ v0,
                                             const float* __restrict__ W,
                                             float* __restrict__ out) {
    __shared__ __align__(16) float sWt[64 * 66];   // sWt[k*66 + c] = W[c][k]
    __shared__ float sX[2][4][D];                  // double-buffered
    const int tid = threadIdx.x;
    const int w   = tid >> 5;                  // warp = local row
    const int l   = tid & 31;
    const int row = blockIdx.x * 4 + w;        // 0..191
    const int c0  = 2 * l;
    const float dt = 0.01f;
    const bool is_state = (row < N);
    const int a = row - N;

    // Coalesced W fill (reads W[c][k] linearly, writes transposed).
    for (int idx = tid; idx < D * D; idx += 128) {
        const int c = idx >> 6, k = idx & 63;
        sWt[k * 66 + c] = W[idx];
    }
    __syncthreads();

    // M columns c0, c0+1 into registers via conflict-free float2 LDS.
    float mA[D], mB[D];
#pragma unroll
    for (int k = 0; k < D; k++) {
        const float2 wv = *(const float2*)&sWt[k * 66 + c0];
        mA[k] = wv.x - (k == c0     ? 1.0f : 0.0f);
        mB[k] = wv.y - (k == c0 + 1 ? 1.0f : 0.0f);
    }

    float2 xl, vl;
    if (is_state) {
        xl = *(const float2*)(x0 + (size_t)row * D + c0);
        vl = *(const float2*)(v0 + (size_t)row * D + c0);
    } else {
        xl = make_float2(c0 == a ? dt * dt : 0.0f, (c0 + 1) == a ? dt * dt : 0.0f);
        vl = make_float2(c0 == a ? dt      : 0.0f, (c0 + 1) == a ? dt      : 0.0f);
    }

    // t = 0 outputs (all coalesced).
    if (is_state) {
        *(float2*)(out + (size_t)row * D + c0) = xl;          // traj frame 0
        __nv_bfloat16 h0, h1, g0, g1;
        bf16split(xl.x, h0, h1); bf16split(xl.y, g0, g1);
        *(__nv_bfloat162*)&g_B0[(size_t)row * D + c0] = {h0, g0};
        *(__nv_bfloat162*)&g_B1[(size_t)row * D + c0] = {h1, g1};
    } else {
        *(float2*)&g_RP[0][a * D + c0] = xl;                  // Xp_0 row a
    }

    *(float2*)&sX[0][w][c0] = xl;
    __syncwarp();

    int p = 0;
#pragma unroll 2
    for (int t = 1; t <= NSTEPS; t++) {
        float2 y0 = make_float2(0.0f, 0.0f);
        float2 y1 = make_float2(0.0f, 0.0f);
#pragma unroll
        for (int k = 0; k < D; k += 2) {
            const float2 xk = *(const float2*)&sX[p][w][k];
            y0.x += xk.x * mA[k];     y0.y += xk.x * mB[k];
            y1.x += xk.y * mA[k + 1]; y1.y += xk.y * mB[k + 1];
        }
        vl.x += dt * (y0.x + y1.x);  vl.y += dt * (y0.y + y1.y);
        xl.x += dt * vl.x;           xl.y += dt * vl.y;
        // Write the OTHER buffer: no WAR hazard, single RAW syncwarp.
        *(float2*)&sX[1 - p][w][c0] = xl;
        __syncwarp();
        p = 1 - p;

        if (is_state) {
            if (t < NSTEPS) {
                __nv_bfloat16 h0, h1, g0, g1;
                bf16split(xl.x, h0, h1); bf16split(xl.y, g0, g1);
                const size_t o = (size_t)t * NCOLS + (size_t)row * D + c0;
                *(__nv_bfloat162*)&g_B0[o] = {h0, g0};
                *(__nv_bfloat162*)&g_B1[o] = {h1, g1};
            }
            if ((t & 3) == 0) {
                float* o = out + (size_t)(t >> 2) * NCOLS + (size_t)row * D + c0;
                *(float2*)o = xl;
            }
        } else if (t < NSTEPS) {
            *(float2*)&g_RP[t][a * D + c0] = xl;              // coalesced
        }
    }
}

// KSPLITA: A-side split only (B is produced by kprep directly).
//  A[r=(i,a)][s] = Xp_{15-s}[a][i] = g_RP[15-s][a*64 + i]   (65536 elements)
// Gathered reads from L2-resident g_RP; coalesced writes.
__global__ void __launch_bounds__(256) ksplitA() {
    const int idx = blockIdx.x * 256 + threadIdx.x;
    const int r = idx >> 4, s = idx & 15;
    const int i = r >> 6, aa = r & 63;
    const float f  = g_RP[15 - s][aa * D + i];
    const __nv_bfloat16 h0 = __float2bfloat16_rn(f);
    g_A0[idx] = h0;
    g_A1[idx] = __float2bfloat16_rn(f - __bfloat162float(h0));
}

// K4: C[(i,a)][(n,b)] = sum_s A[(i,a)][s] * B[s][(n,b)]  — one 4096x8192x16
// GEMM via wmma 16x16x16 bf16, 3-pass split-bf16 (a0b0 + a0b1 + a1b0).
// Epilogue: per (warp, mt) the 4 nt tiles form one 16(a) x 64(b) region whose
// rows are complete 256B jac rows. Stage them in a per-warp smem buffer, then
// copy with STG.128 covering 2 full rows each (ideal coalescing) — removes
// store_matrix_sync's 32B-per-row scatter (the L1=76% wall). Register cap
// (256,4) + per-tile b-frag reloads keep occupancy (R13's failure mode).
constexpr int ALD = 24;    // bf16 smem ldm for A (16 + 8 pad)
constexpr int BLD = 136;   // bf16 smem ldm for B (128 + 8 pad)
constexpr int CLD = 68;    // f32 smem ldm for C staging (64 + 4 pad)
constexpr size_t K4_ABYTES = 128 * ALD * 2;          // 6144 per split
constexpr size_t K4_BBYTES = 16 * BLD * 2;           // 4352 per split
constexpr size_t K4_CBYTES = 8 * 16 * CLD * 4;       // 34816
constexpr size_t K4_SMEM   = 2 * K4_ABYTES + 2 * K4_BBYTES + K4_CBYTES; // 55936

__global__ void __launch_bounds__(256, 4) k4_jac(float* __restrict__ jac) {
    extern __shared__ __align__(16) char dyn[];
    __nv_bfloat16* sA0 = (__nv_bfloat16*)dyn;
    __nv_bfloat16* sA1 = sA0 + 128 * ALD;
    __nv_bfloat16* sB0 = sA1 + 128 * ALD;
    __nv_bfloat16* sB1 = sB0 + 16 * BLD;
    float*         sC  = (float*)(sB1 + 16 * BLD);
    const int tid = threadIdx.x, bid = blockIdx.x;
    const int m0 = (bid & 31) * 128;   // 32 M-blocks
    const int n0 = (bid >> 5) * 128;   // 64 N-blocks

    // Stage A (128 rows x 16 bf16) and B (16 rows x 128 bf16), both splits.
    {
        const int row = tid >> 1, q = (tid & 1) << 3;
        *(float4*)&sA0[row * ALD + q] =
            *(const float4*)&g_A0[(size_t)(m0 + row) * NSTEPS + q];
        *(float4*)&sA1[row * ALD + q] =
            *(const float4*)&g_A1[(size_t)(m0 + row) * NSTEPS + q];
        const int s = tid >> 4, bq = (tid & 15) << 3;
        *(float4*)&sB0[s * BLD + bq] =
            *(const float4*)&g_B0[(size_t)s * NCOLS + n0 + bq];
        *(float4*)&sB1[s * BLD + bq] =
            *(const float4*)&g_B1[(size_t)s * NCOLS + n0 + bq];
    }
    __syncthreads();

    const int wid = tid >> 5, lane = tid & 31;
    const int wm = wid & 3, wn = wid >> 2;
    float* sCw = sC + wid * 16 * CLD;

    wmma::fragment<wmma::matrix_a, 16, 16, 16, __nv_bfloat16,
                   wmma::row_major> a0f[2], a1f[2];
#pragma unroll
    for (int mt = 0; mt < 2; mt++) {
        const int ro = (wm * 32 + mt * 16) * ALD;
        wmma::load_matrix_sync(a0f[mt], &sA0[ro], ALD);
        wmma::load_matrix_sync(a1f[mt], &sA1[ro], ALD);
    }

#pragma unroll
    for (int mt = 0; mt < 2; mt++) {
#pragma unroll
        for (int nt = 0; nt < 4; nt++) {
            const int cl = wn * 64 + nt * 16;
            wmma::fragment<wmma::matrix_b, 16, 16, 16, __nv_bfloat16,
                           wmma::row_major> b0f, b1f;
            wmma::load_matrix_sync(b0f, &sB0[cl], BLD);
            wmma::load_matrix_sync(b1f, &sB1[cl], BLD);
            wmma::fragment<wmma::accumulator, 16, 16, 16, float> acc;
            wmma::fill_fragment(acc, 0.0f);
            wmma::mma_sync(acc, a0f[mt], b0f, acc);
            wmma::mma_sync(acc, a0f[mt], b1f, acc);
            wmma::mma_sync(acc, a1f[mt], b0f, acc);
            wmma::store_matrix_sync(&sCw[nt * 16], acc, CLD,
                                    wmma::mem_row_major);
        }
        __syncwarp();
        // Copy 16(a) x 64(b) f32 -> jac; each STG.128 covers 2 full 256B rows.
        const int r = m0 + wm * 32 + mt * 16;   // (i,a): i = r>>6, a0 = r&63
        const int c = n0 + wn * 64;             // (n,b): b = 0..63 full rows
        float* dst = jac + (size_t)(c >> 6) * (64 * 64 * 64)
                   + (size_t)(r >> 6) * (64 * 64)
                   + (size_t)(r & 63) * 64;
#pragma unroll
        for (int it = 0; it < 8; it++) {
            const int idx = it * 32 + lane;     // 256 float4 chunks
            const int rr = idx >> 4, q = (idx & 15) << 2;
            *(float4*)&dst[(size_t)rr * 64 + q] = *(float4*)&sCw[rr * CLD + q];
        }
        __syncwarp();
    }
}

extern "C" void kernel_launch(void* const* d_in, const int* in_sizes, int n_in,
                              void* d_out, int out_size) {
    const float* x0 = (const float*)d_in[0];
    const float* v0 = (const float*)d_in[1];
    const float* W  = (const float*)d_in[2];
    float* out = (float*)d_out;
    // output = [traj (frames x N x D)] then [jac (N x D x D x D)]
    float* jac = out + ((size_t)out_size - (size_t)N * D * D * D);

    static bool attr_set = false;
    if (!attr_set) {
        cudaFuncSetAttribute(k4_jac, cudaFuncAttributeMaxDynamicSharedMemorySize,
                             (int)K4_SMEM);
        attr_set = true;
    }

    kprep<<<48, 128>>>(x0, v0, W, out);
    ksplitA<<<MROWS * NSTEPS / 256, 256>>>();
    k4_jac<<<2048, 256, K4_SMEM>>>(jac);
}